// round 15
// baseline (speedup 1.0000x reference)
#include <cuda_runtime.h>
#include <cuda_bf16.h>
#include <stdint.h>
#include <stddef.h>

#define IN_F  4096
#define OUT_F 14336
#define M_ROWS 1024

#define BM 128
#define BN 224                      // 14336 = 64 * 224 exactly
#define BK 64
#define ROWB 144                    // padded smem row stride (bytes)
#define NSTAGES 3
#define K_TILES (IN_F / BK)         // 64
#define A_BYTES (BM * ROWB)         // 18432
#define B_BYTES (BN * ROWB)         // 32256
#define STAGE_BYTES (A_BYTES + B_BYTES)        // 50688
#define SMEM_DYN_BYTES (NSTAGES * STAGE_BYTES) // 152064

// scratch (device globals are allowed)
__device__ __nv_bfloat16 g_wbf16[(size_t)OUT_F * IN_F];   // bf16(w_f8 * scale)
__device__ __nv_bfloat16 g_xbf16[(size_t)M_ROWS * IN_F];  // bf16(x)

// ---------------- helpers ----------------
__device__ __forceinline__ uint32_t smem_u32(const void* p) {
    uint32_t a;
    asm("{ .reg .u64 t; cvta.to.shared.u64 t, %1; cvt.u32.u64 %0, t; }" : "=r"(a) : "l"(p));
    return a;
}
__device__ __forceinline__ void cp_async16(uint32_t dst, const void* src) {
    asm volatile("cp.async.cg.shared.global [%0], [%1], 16;\n" :: "r"(dst), "l"(src));
}
#define CP_COMMIT() asm volatile("cp.async.commit_group;\n" ::: "memory")

__device__ __forceinline__ void ldsm_x4(uint32_t* r, uint32_t addr) {
    asm volatile("ldmatrix.sync.aligned.m8n8.x4.shared.b16 {%0,%1,%2,%3}, [%4];"
                 : "=r"(r[0]), "=r"(r[1]), "=r"(r[2]), "=r"(r[3]) : "r"(addr));
}
__device__ __forceinline__ void mma_bf16(float* c, const uint32_t* a, uint32_t b0, uint32_t b1) {
    asm volatile(
        "mma.sync.aligned.m16n8k16.row.col.f32.bf16.bf16.f32 "
        "{%0,%1,%2,%3}, {%4,%5,%6,%7}, {%8,%9}, {%0,%1,%2,%3};"
        : "+f"(c[0]), "+f"(c[1]), "+f"(c[2]), "+f"(c[3])
        : "r"(a[0]), "r"(a[1]), "r"(a[2]), "r"(a[3]), "r"(b0), "r"(b1));
}
__device__ __forceinline__ uint32_t pack2(float a, float b) {
    __nv_bfloat162 h = __floats2bfloat162_rn(a, b);
    return *reinterpret_cast<uint32_t*>(&h);
}

// ---------------- x convert: f32 (bf16-valued) -> bf16, exact ----------------
__global__ void convert_x_kernel(const float4* __restrict__ xf32) {
    size_t total8 = (size_t)M_ROWS * IN_F / 8;
    size_t stride = (size_t)gridDim.x * blockDim.x;
    uint4* __restrict__ dst = reinterpret_cast<uint4*>(g_xbf16);
    for (size_t i = (size_t)blockIdx.x * blockDim.x + threadIdx.x; i < total8; i += stride) {
        float4 v0 = xf32[2 * i];
        float4 v1 = xf32[2 * i + 1];
        uint4 o;
        o.x = pack2(v0.x, v0.y); o.y = pack2(v0.z, v0.w);
        o.z = pack2(v1.x, v1.y); o.w = pack2(v1.z, v1.w);
        dst[i] = o;
    }
}

// ---------------- w dequant: f32 (fp8-valued) * bf16(scale) -> bf16 ----------------
__global__ void convert_w_kernel(const float4* __restrict__ wf8, const float* __restrict__ wscale) {
    float s = __bfloat162float(__float2bfloat16(wscale[0]));   // bf16(scale), exact in f32
    size_t total8 = (size_t)OUT_F * IN_F / 8;
    size_t stride = (size_t)gridDim.x * blockDim.x;
    uint4* __restrict__ dst = reinterpret_cast<uint4*>(g_wbf16);
    for (size_t i = (size_t)blockIdx.x * blockDim.x + threadIdx.x; i < total8; i += stride) {
        float4 v0 = wf8[2 * i];
        float4 v1 = wf8[2 * i + 1];
        uint4 o;
        o.x = pack2(v0.x * s, v0.y * s); o.y = pack2(v0.z * s, v0.w * s);
        o.z = pack2(v1.x * s, v1.y * s); o.w = pack2(v1.z * s, v1.w * s);
        dst[i] = o;
    }
}

// ---------------- stage loader (256 threads) ----------------
__device__ __forceinline__ void load_stage(uint32_t data_base, int slot,
                                           int m0, int n0, int kt, int tid) {
    uint32_t aBase = data_base + (uint32_t)slot * STAGE_BYTES;
    uint32_t bBase = aBase + A_BYTES;
    const __nv_bfloat16* __restrict__ xa = g_xbf16;
    const __nv_bfloat16* __restrict__ w  = g_wbf16;
#pragma unroll
    for (int i = 0; i < 4; i++) {                 // A: 128 rows x 8 x 16B
        int idx = tid + i * 256;
        int r = idx >> 3, c = idx & 7;
        cp_async16(aBase + (uint32_t)(r * ROWB + c * 16),
                   xa + (size_t)(m0 + r) * IN_F + kt * BK + c * 8);
    }
#pragma unroll
    for (int i = 0; i < 7; i++) {                 // B: 224 rows x 8 x 16B = 1792 chunks
        int idx = tid + i * 256;
        int r = idx >> 3, c = idx & 7;
        cp_async16(bBase + (uint32_t)(r * ROWB + c * 16),
                   w + (size_t)(n0 + r) * IN_F + kt * BK + c * 8);
    }
}

// ---------------- GEMM (f32 output, N elements, positional) ----------------
__global__ void __launch_bounds__(256, 1)
f8linear_gemm(const float* __restrict__ bias, float* __restrict__ out) {
    extern __shared__ char dynsmem[];
    const int tid = threadIdx.x;
    const int bid = blockIdx.x;
    const int wid = tid >> 5;
    const int lane = tid & 31;
    const int m0 = (bid & 7) * BM;     // m-fast: 8 CTAs share one weight strip in L2
    const int n0 = (bid >> 3) * BN;

    const uint32_t data_base = smem_u32(dynsmem);
    const int wm = wid >> 1;           // 0..3: 32-row warp tile
    const int wn = wid & 1;            // 0..1: 112-col warp tile
    const int grp = lane >> 3;
    const int rn  = lane & 7;

    const int aRowBase = wm * 32 + (grp & 1) * 8 + rn;    // + mi*16 (mi 0..1)
    const int aColSel  = (grp >> 1) * 16;                 // + ks*32
    const int bRowBase = wn * 112 + (grp >> 1) * 8 + rn;  // + nj*16 (nj 0..6)
    const int bColSel  = (grp & 1) * 16;

    float c[2][14][4];
#pragma unroll
    for (int mi = 0; mi < 2; mi++)
#pragma unroll
        for (int ni = 0; ni < 14; ni++)
#pragma unroll
            for (int k = 0; k < 4; k++) c[mi][ni][k] = 0.0f;

    for (int p = 0; p < NSTAGES - 1; p++) {
        load_stage(data_base, p, m0, n0, p, tid);
        CP_COMMIT();
    }

    for (int kt = 0; kt < K_TILES; kt++) {
        const int slot = kt % NSTAGES;
        asm volatile("cp.async.wait_group %0;\n" :: "n"(NSTAGES - 2) : "memory");
        __syncthreads();

        const uint32_t aSlot = data_base + (uint32_t)slot * STAGE_BYTES;
        const uint32_t bSlot = aSlot + A_BYTES;

#pragma unroll
        for (int ks = 0; ks < 4; ks++) {
            uint32_t a[2][4], b[7][4];
#pragma unroll
            for (int mi = 0; mi < 2; mi++)
                ldsm_x4(a[mi], aSlot + (uint32_t)((aRowBase + mi * 16) * ROWB + ks * 32 + aColSel));
#pragma unroll
            for (int nj = 0; nj < 7; nj++)
                ldsm_x4(b[nj], bSlot + (uint32_t)((bRowBase + nj * 16) * ROWB + ks * 32 + bColSel));
#pragma unroll
            for (int mi = 0; mi < 2; mi++)
#pragma unroll
                for (int nj = 0; nj < 7; nj++) {
                    mma_bf16(c[mi][2 * nj],     a[mi], b[nj][0], b[nj][1]);
                    mma_bf16(c[mi][2 * nj + 1], a[mi], b[nj][2], b[nj][3]);
                }
        }

        const int lt = kt + NSTAGES - 1;
        if (lt < K_TILES) load_stage(data_base, lt % NSTAGES, m0, n0, lt, tid);
        CP_COMMIT();
    }

    // epilogue: f32( bf16( bf16(acc) + bf16(bias) ) ), stored as f32 positional
    const int rbase = m0 + wm * 32 + (lane >> 2);
    const int cbase = n0 + wn * 112 + (lane & 3) * 2;
#pragma unroll
    for (int mi = 0; mi < 2; mi++) {
#pragma unroll
        for (int ni = 0; ni < 14; ni++) {
            int gm = rbase + mi * 16;
            int gn = cbase + ni * 8;
            float b0 = __bfloat162float(__float2bfloat16(bias[gn]));
            float b1 = __bfloat162float(__float2bfloat16(bias[gn + 1]));
            float s00 = __bfloat162float(__float2bfloat16(c[mi][ni][0]));
            float s01 = __bfloat162float(__float2bfloat16(c[mi][ni][1]));
            float s10 = __bfloat162float(__float2bfloat16(c[mi][ni][2]));
            float s11 = __bfloat162float(__float2bfloat16(c[mi][ni][3]));
            float2 v0 = make_float2(__bfloat162float(__float2bfloat16(s00 + b0)),
                                    __bfloat162float(__float2bfloat16(s01 + b1)));
            float2 v1 = make_float2(__bfloat162float(__float2bfloat16(s10 + b0)),
                                    __bfloat162float(__float2bfloat16(s11 + b1)));
            *reinterpret_cast<float2*>(out + (size_t)gm * OUT_F + gn) = v0;
            *reinterpret_cast<float2*>(out + (size_t)(gm + 8) * OUT_F + gn) = v1;
        }
    }
}

// ---------------- launch ----------------
extern "C" void kernel_launch(void* const* d_in, const int* in_sizes, int n_in,
                              void* d_out, int out_size) {
    (void)out_size;
    const float* xf32   = nullptr;   // 4194304  f32 (bf16-valued)
    const float* wf8    = nullptr;   // 58720256 f32 (fp8-valued)
    const float* wscale = nullptr;   // 1        f32
    const float* bias   = nullptr;   // 14336    f32
    for (int i = 0; i < n_in; i++) {
        switch (in_sizes[i]) {
            case 4194304:  xf32   = (const float*)d_in[i]; break;
            case 58720256: wf8    = (const float*)d_in[i]; break;
            case 1:        wscale = (const float*)d_in[i]; break;
            case 14336:    bias   = (const float*)d_in[i]; break;
            default: break;
        }
    }
    float* out = (float*)d_out;

    convert_x_kernel<<<1024, 256>>>(reinterpret_cast<const float4*>(xf32));
    convert_w_kernel<<<2048, 256>>>(reinterpret_cast<const float4*>(wf8), wscale);

    cudaFuncSetAttribute(f8linear_gemm, cudaFuncAttributeMaxDynamicSharedMemorySize,
                         SMEM_DYN_BYTES);
    int grid = (M_ROWS / BM) * (OUT_F / BN);   // 8 * 64 = 512
    f8linear_gemm<<<grid, 256, SMEM_DYN_BYTES>>>(bias, out);
}

// round 16
// speedup vs baseline: 1.7264x; 1.7264x over previous
#include <cuda_runtime.h>
#include <cuda_bf16.h>
#include <stdint.h>
#include <stddef.h>

#define IN_F  4096
#define OUT_F 14336
#define M_ROWS 1024

#define BM 128
#define BN 256
#define BK 64
#define ROWB 144                    // padded smem row stride (bytes)
#define NSTAGES 3
#define K_TILES (IN_F / BK)         // 64
#define A_BYTES (BM * ROWB)         // 18432
#define B_BYTES (BN * ROWB)         // 36864
#define STAGE_BYTES (A_BYTES + B_BYTES)        // 55296
#define SMEM_DYN_BYTES (NSTAGES * STAGE_BYTES) // 165888

#define N_STRIPS (OUT_F / BN)       // 56
#define MS_ROWS (BN / 8)            // 32 rows converted per CTA

// scratch (device globals are allowed)
__device__ __nv_bfloat16 g_wbf16[(size_t)OUT_F * IN_F];   // bf16(w_f8 * scale)
__device__ __nv_bfloat16 g_xbf16[(size_t)M_ROWS * IN_F];  // bf16(x)
__device__ unsigned int  g_ready[N_STRIPS];               // per-strip arrival counters

// ---------------- helpers ----------------
__device__ __forceinline__ uint32_t smem_u32(const void* p) {
    uint32_t a;
    asm("{ .reg .u64 t; cvta.to.shared.u64 t, %1; cvt.u32.u64 %0, t; }" : "=r"(a) : "l"(p));
    return a;
}
__device__ __forceinline__ void cp_async16(uint32_t dst, const void* src) {
    asm volatile("cp.async.cg.shared.global [%0], [%1], 16;\n" :: "r"(dst), "l"(src));
}
#define CP_COMMIT() asm volatile("cp.async.commit_group;\n" ::: "memory")

__device__ __forceinline__ void ldsm_x4(uint32_t* r, uint32_t addr) {
    asm volatile("ldmatrix.sync.aligned.m8n8.x4.shared.b16 {%0,%1,%2,%3}, [%4];"
                 : "=r"(r[0]), "=r"(r[1]), "=r"(r[2]), "=r"(r[3]) : "r"(addr));
}
__device__ __forceinline__ void mma_bf16(float* c, const uint32_t* a, uint32_t b0, uint32_t b1) {
    asm volatile(
        "mma.sync.aligned.m16n8k16.row.col.f32.bf16.bf16.f32 "
        "{%0,%1,%2,%3}, {%4,%5,%6,%7}, {%8,%9}, {%0,%1,%2,%3};"
        : "+f"(c[0]), "+f"(c[1]), "+f"(c[2]), "+f"(c[3])
        : "r"(a[0]), "r"(a[1]), "r"(a[2]), "r"(a[3]), "r"(b0), "r"(b1));
}
__device__ __forceinline__ uint32_t pack2(float a, float b) {
    __nv_bfloat162 h = __floats2bfloat162_rn(a, b);
    return *reinterpret_cast<uint32_t*>(&h);
}
__device__ __forceinline__ unsigned int ld_acquire(const unsigned int* p) {
    unsigned int v;
    asm volatile("ld.acquire.gpu.u32 %0, [%1];" : "=r"(v) : "l"(p) : "memory");
    return v;
}

// ---------------- x convert + counter reset ----------------
__global__ void convert_x_kernel(const float4* __restrict__ xf32) {
    if (blockIdx.x == 0 && threadIdx.x < N_STRIPS) g_ready[threadIdx.x] = 0;
    size_t total8 = (size_t)M_ROWS * IN_F / 8;
    size_t stride = (size_t)gridDim.x * blockDim.x;
    uint4* __restrict__ dst = reinterpret_cast<uint4*>(g_xbf16);
    for (size_t i = (size_t)blockIdx.x * blockDim.x + threadIdx.x; i < total8; i += stride) {
        float4 v0 = xf32[2 * i];
        float4 v1 = xf32[2 * i + 1];
        uint4 o;
        o.x = pack2(v0.x, v0.y); o.y = pack2(v0.z, v0.w);
        o.z = pack2(v1.x, v1.y); o.w = pack2(v1.z, v1.w);
        dst[i] = o;
    }
}

// ---------------- stage loader (256 threads) ----------------
__device__ __forceinline__ void load_stage(uint32_t data_base, int slot,
                                           int m0, int n0, int kt, int tid) {
    uint32_t aBase = data_base + (uint32_t)slot * STAGE_BYTES;
    uint32_t bBase = aBase + A_BYTES;
    const __nv_bfloat16* __restrict__ xa = g_xbf16;
    const __nv_bfloat16* __restrict__ w  = g_wbf16;
#pragma unroll
    for (int i = 0; i < 4; i++) {                 // A: 128 rows x 8 x 16B
        int idx = tid + i * 256;
        int r = idx >> 3, c = idx & 7;
        cp_async16(aBase + (uint32_t)(r * ROWB + c * 16),
                   xa + (size_t)(m0 + r) * IN_F + kt * BK + c * 8);
    }
#pragma unroll
    for (int i = 0; i < 8; i++) {                 // B: 256 rows x 8 x 16B
        int idx = tid + i * 256;
        int r = idx >> 3, c = idx & 7;
        cp_async16(bBase + (uint32_t)(r * ROWB + c * 16),
                   w + (size_t)(n0 + r) * IN_F + kt * BK + c * 8);
    }
}

// ---------------- GEMM with fused cooperative w-dequant ----------------
__global__ void __launch_bounds__(256, 1)
f8linear_gemm(const float4* __restrict__ wf8,
              const float* __restrict__ wscale,
              const float* __restrict__ bias,
              float* __restrict__ out) {
    extern __shared__ char dynsmem[];
    const int tid = threadIdx.x;
    const int bid = blockIdx.x;
    const int wid = tid >> 5;
    const int lane = tid & 31;
    const int mslice = bid & 7;        // also this CTA's conversion slice index
    const int strip  = bid >> 3;       // n-strip index
    const int m0 = mslice * BM;        // m-fast: 8 CTAs share one weight strip in L2
    const int n0 = strip * BN;

    // ---- fused dequant: convert rows [n0 + mslice*32, +32) of w ----
    {
        const float s = __bfloat162float(__float2bfloat16(wscale[0]));
        const size_t row0 = (size_t)(n0 + mslice * MS_ROWS) * IN_F;
        const float4* __restrict__ src = wf8 + row0 / 4;
        uint4* __restrict__ dst = reinterpret_cast<uint4*>(g_wbf16 + row0);
        const int total = MS_ROWS * IN_F / 8;   // 16384 uint4 outputs
#pragma unroll 4
        for (int j = tid; j < total; j += 256) {
            float4 v0 = src[2 * j];
            float4 v1 = src[2 * j + 1];
            uint4 o;
            o.x = pack2(v0.x * s, v0.y * s); o.y = pack2(v0.z * s, v0.w * s);
            o.z = pack2(v1.x * s, v1.y * s); o.w = pack2(v1.z * s, v1.w * s);
            dst[j] = o;
        }
        __threadfence();                 // make this thread's slice writes gpu-visible
        __syncthreads();
        if (tid == 0) atomicAdd(&g_ready[strip], 1u);
        // wait until all 8 slices of this strip are converted
        if (tid == 0) {
            while (ld_acquire(&g_ready[strip]) < 8u) { }
        }
        __syncthreads();
    }

    const uint32_t data_base = smem_u32(dynsmem);
    const int wm = wid >> 2;
    const int wn = wid & 3;
    const int grp = lane >> 3;
    const int rn  = lane & 7;

    const int aRowBase = wm * 64 + (grp & 1) * 8 + rn;
    const int aColSel  = (grp >> 1) * 16;
    const int bRowBase = wn * 64 + (grp >> 1) * 8 + rn;
    const int bColSel  = (grp & 1) * 16;

    float c[4][8][4];
#pragma unroll
    for (int mi = 0; mi < 4; mi++)
#pragma unroll
        for (int ni = 0; ni < 8; ni++)
#pragma unroll
            for (int k = 0; k < 4; k++) c[mi][ni][k] = 0.0f;

    for (int p = 0; p < NSTAGES - 1; p++) {
        load_stage(data_base, p, m0, n0, p, tid);
        CP_COMMIT();
    }

    for (int kt = 0; kt < K_TILES; kt++) {
        const int slot = kt % NSTAGES;
        asm volatile("cp.async.wait_group %0;\n" :: "n"(NSTAGES - 2) : "memory");
        __syncthreads();

        const uint32_t aSlot = data_base + (uint32_t)slot * STAGE_BYTES;
        const uint32_t bSlot = aSlot + A_BYTES;

#pragma unroll
        for (int ks = 0; ks < 4; ks++) {
            uint32_t a[4][4], b[4][4];
#pragma unroll
            for (int mi = 0; mi < 4; mi++)
                ldsm_x4(a[mi], aSlot + (uint32_t)((aRowBase + mi * 16) * ROWB + ks * 32 + aColSel));
#pragma unroll
            for (int nj = 0; nj < 4; nj++)
                ldsm_x4(b[nj], bSlot + (uint32_t)((bRowBase + nj * 16) * ROWB + ks * 32 + bColSel));
#pragma unroll
            for (int mi = 0; mi < 4; mi++)
#pragma unroll
                for (int nj = 0; nj < 4; nj++) {
                    mma_bf16(c[mi][2 * nj],     a[mi], b[nj][0], b[nj][1]);
                    mma_bf16(c[mi][2 * nj + 1], a[mi], b[nj][2], b[nj][3]);
                }
        }

        const int lt = kt + NSTAGES - 1;
        if (lt < K_TILES) load_stage(data_base, lt % NSTAGES, m0, n0, lt, tid);
        CP_COMMIT();
    }

    // epilogue: f32( bf16( bf16(acc) + bf16(bias) ) ), stored as f32 positional
    const int rbase = m0 + wm * 64 + (lane >> 2);
    const int cbase = n0 + wn * 64 + (lane & 3) * 2;
#pragma unroll
    for (int mi = 0; mi < 4; mi++) {
#pragma unroll
        for (int ni = 0; ni < 8; ni++) {
            int gm = rbase + mi * 16;
            int gn = cbase + ni * 8;
            float b0 = __bfloat162float(__float2bfloat16(bias[gn]));
            float b1 = __bfloat162float(__float2bfloat16(bias[gn + 1]));
            float s00 = __bfloat162float(__float2bfloat16(c[mi][ni][0]));
            float s01 = __bfloat162float(__float2bfloat16(c[mi][ni][1]));
            float s10 = __bfloat162float(__float2bfloat16(c[mi][ni][2]));
            float s11 = __bfloat162float(__float2bfloat16(c[mi][ni][3]));
            float2 v0 = make_float2(__bfloat162float(__float2bfloat16(s00 + b0)),
                                    __bfloat162float(__float2bfloat16(s01 + b1)));
            float2 v1 = make_float2(__bfloat162float(__float2bfloat16(s10 + b0)),
                                    __bfloat162float(__float2bfloat16(s11 + b1)));
            *reinterpret_cast<float2*>(out + (size_t)gm * OUT_F + gn) = v0;
            *reinterpret_cast<float2*>(out + (size_t)(gm + 8) * OUT_F + gn) = v1;
        }
    }
}

// ---------------- launch ----------------
extern "C" void kernel_launch(void* const* d_in, const int* in_sizes, int n_in,
                              void* d_out, int out_size) {
    (void)out_size;
    const float* xf32   = nullptr;   // 4194304  f32 (bf16-valued)
    const float* wf8    = nullptr;   // 58720256 f32 (fp8-valued)
    const float* wscale = nullptr;   // 1        f32
    const float* bias   = nullptr;   // 14336    f32
    for (int i = 0; i < n_in; i++) {
        switch (in_sizes[i]) {
            case 4194304:  xf32   = (const float*)d_in[i]; break;
            case 58720256: wf8    = (const float*)d_in[i]; break;
            case 1:        wscale = (const float*)d_in[i]; break;
            case 14336:    bias   = (const float*)d_in[i]; break;
            default: break;
        }
    }
    float* out = (float*)d_out;

    convert_x_kernel<<<1024, 256>>>(reinterpret_cast<const float4*>(xf32));

    cudaFuncSetAttribute(f8linear_gemm, cudaFuncAttributeMaxDynamicSharedMemorySize,
                         SMEM_DYN_BYTES);
    int grid = (M_ROWS / BM) * (OUT_F / BN);   // 448
    f8linear_gemm<<<grid, 256, SMEM_DYN_BYTES>>>(
        reinterpret_cast<const float4*>(wf8), wscale, bias, out);
}

// round 17
// speedup vs baseline: 1.8720x; 1.0843x over previous
#include <cuda_runtime.h>
#include <cuda_bf16.h>
#include <stdint.h>
#include <stddef.h>

#define IN_F  4096
#define OUT_F 14336
#define M_ROWS 1024

#define BM 128
#define BN 128
#define BK 64
#define ROWB 144                    // padded smem row stride (bytes)
#define NSTAGES 3
#define K_TILES (IN_F / BK)         // 64
#define A_BYTES (BM * ROWB)         // 18432
#define B_BYTES (BN * ROWB)         // 18432
#define STAGE_BYTES (A_BYTES + B_BYTES)        // 36864
#define SMEM_DYN_BYTES (NSTAGES * STAGE_BYTES) // 110592  (x2 CTAs = 221184 <= 228KB)

#define N_STRIPS (OUT_F / BN)       // 112
#define MS_ROWS (BN / 8)            // 16 rows converted per CTA

// scratch (device globals are allowed)
__device__ __nv_bfloat16 g_wbf16[(size_t)OUT_F * IN_F];   // bf16(w_f8 * scale)
__device__ __nv_bfloat16 g_xbf16[(size_t)M_ROWS * IN_F];  // bf16(x)
__device__ unsigned int  g_ready[N_STRIPS];               // per-strip arrival counters

// ---------------- helpers ----------------
__device__ __forceinline__ uint32_t smem_u32(const void* p) {
    uint32_t a;
    asm("{ .reg .u64 t; cvta.to.shared.u64 t, %1; cvt.u32.u64 %0, t; }" : "=r"(a) : "l"(p));
    return a;
}
__device__ __forceinline__ void cp_async16(uint32_t dst, const void* src) {
    asm volatile("cp.async.cg.shared.global [%0], [%1], 16;\n" :: "r"(dst), "l"(src));
}
#define CP_COMMIT() asm volatile("cp.async.commit_group;\n" ::: "memory")

__device__ __forceinline__ void ldsm_x4(uint32_t* r, uint32_t addr) {
    asm volatile("ldmatrix.sync.aligned.m8n8.x4.shared.b16 {%0,%1,%2,%3}, [%4];"
                 : "=r"(r[0]), "=r"(r[1]), "=r"(r[2]), "=r"(r[3]) : "r"(addr));
}
__device__ __forceinline__ void mma_bf16(float* c, const uint32_t* a, uint32_t b0, uint32_t b1) {
    asm volatile(
        "mma.sync.aligned.m16n8k16.row.col.f32.bf16.bf16.f32 "
        "{%0,%1,%2,%3}, {%4,%5,%6,%7}, {%8,%9}, {%0,%1,%2,%3};"
        : "+f"(c[0]), "+f"(c[1]), "+f"(c[2]), "+f"(c[3])
        : "r"(a[0]), "r"(a[1]), "r"(a[2]), "r"(a[3]), "r"(b0), "r"(b1));
}
__device__ __forceinline__ uint32_t pack2(float a, float b) {
    __nv_bfloat162 h = __floats2bfloat162_rn(a, b);
    return *reinterpret_cast<uint32_t*>(&h);
}
__device__ __forceinline__ unsigned int ld_acquire(const unsigned int* p) {
    unsigned int v;
    asm volatile("ld.acquire.gpu.u32 %0, [%1];" : "=r"(v) : "l"(p) : "memory");
    return v;
}

// ---------------- x convert + counter reset ----------------
__global__ void convert_x_kernel(const float4* __restrict__ xf32) {
    if (blockIdx.x == 0 && threadIdx.x < N_STRIPS) g_ready[threadIdx.x] = 0;
    size_t total8 = (size_t)M_ROWS * IN_F / 8;
    size_t stride = (size_t)gridDim.x * blockDim.x;
    uint4* __restrict__ dst = reinterpret_cast<uint4*>(g_xbf16);
    for (size_t i = (size_t)blockIdx.x * blockDim.x + threadIdx.x; i < total8; i += stride) {
        float4 v0 = xf32[2 * i];
        float4 v1 = xf32[2 * i + 1];
        uint4 o;
        o.x = pack2(v0.x, v0.y); o.y = pack2(v0.z, v0.w);
        o.z = pack2(v1.x, v1.y); o.w = pack2(v1.z, v1.w);
        dst[i] = o;
    }
}

// ---------------- stage loader (256 threads) ----------------
__device__ __forceinline__ void load_stage(uint32_t data_base, int slot,
                                           int m0, int n0, int kt, int tid) {
    uint32_t aBase = data_base + (uint32_t)slot * STAGE_BYTES;
    uint32_t bBase = aBase + A_BYTES;
    const __nv_bfloat16* __restrict__ xa = g_xbf16;
    const __nv_bfloat16* __restrict__ w  = g_wbf16;
#pragma unroll
    for (int i = 0; i < 4; i++) {                 // A: 128 rows x 8 x 16B
        int idx = tid + i * 256;
        int r = idx >> 3, c = idx & 7;
        cp_async16(aBase + (uint32_t)(r * ROWB + c * 16),
                   xa + (size_t)(m0 + r) * IN_F + kt * BK + c * 8);
    }
#pragma unroll
    for (int i = 0; i < 4; i++) {                 // B: 128 rows x 8 x 16B
        int idx = tid + i * 256;
        int r = idx >> 3, c = idx & 7;
        cp_async16(bBase + (uint32_t)(r * ROWB + c * 16),
                   w + (size_t)(n0 + r) * IN_F + kt * BK + c * 8);
    }
}

// ---------------- GEMM with fused cooperative w-dequant, 2 CTAs/SM ----------------
__global__ void __launch_bounds__(256, 2)
f8linear_gemm(const float4* __restrict__ wf8,
              const float* __restrict__ wscale,
              const float* __restrict__ bias,
              float* __restrict__ out) {
    extern __shared__ char dynsmem[];
    const int tid = threadIdx.x;
    const int bid = blockIdx.x;
    const int wid = tid >> 5;
    const int lane = tid & 31;
    const int mslice = bid & 7;        // conversion slice index within strip
    const int strip  = bid >> 3;       // n-strip index
    const int m0 = mslice * BM;        // m-fast: 8 CTAs share one weight strip in L2
    const int n0 = strip * BN;

    // ---- fused dequant: rows [n0 + mslice*16, +16) of w ----
    {
        const float s = __bfloat162float(__float2bfloat16(wscale[0]));
        const size_t row0 = (size_t)(n0 + mslice * MS_ROWS) * IN_F;
        const float4* __restrict__ src = wf8 + row0 / 4;
        uint4* __restrict__ dst = reinterpret_cast<uint4*>(g_wbf16 + row0);
        const int total = MS_ROWS * IN_F / 8;   // 8192 uint4 outputs
#pragma unroll 4
        for (int j = tid; j < total; j += 256) {
            float4 v0 = src[2 * j];
            float4 v1 = src[2 * j + 1];
            uint4 o;
            o.x = pack2(v0.x * s, v0.y * s); o.y = pack2(v0.z * s, v0.w * s);
            o.z = pack2(v1.x * s, v1.y * s); o.w = pack2(v1.z * s, v1.w * s);
            dst[j] = o;
        }
        __threadfence();
        __syncthreads();
        if (tid == 0) {
            atomicAdd(&g_ready[strip], 1u);
            while (ld_acquire(&g_ready[strip]) < 8u) { }
        }
        __syncthreads();
    }

    const uint32_t data_base = smem_u32(dynsmem);
    const int wm = wid >> 2;           // 0..1: 64-row warp tile
    const int wn = wid & 3;            // 0..3: 32-col warp tile
    const int grp = lane >> 3;
    const int rn  = lane & 7;

    const int aRowBase = wm * 64 + (grp & 1) * 8 + rn;   // + mi*16
    const int aColSel  = (grp >> 1) * 16;                // + ks*32
    const int bRowBase = wn * 32 + (grp >> 1) * 8 + rn;  // + nj*16
    const int bColSel  = (grp & 1) * 16;

    float c[4][4][4];
#pragma unroll
    for (int mi = 0; mi < 4; mi++)
#pragma unroll
        for (int ni = 0; ni < 4; ni++)
#pragma unroll
            for (int k = 0; k < 4; k++) c[mi][ni][k] = 0.0f;

    for (int p = 0; p < NSTAGES - 1; p++) {
        load_stage(data_base, p, m0, n0, p, tid);
        CP_COMMIT();
    }

    for (int kt = 0; kt < K_TILES; kt++) {
        const int slot = kt % NSTAGES;
        asm volatile("cp.async.wait_group %0;\n" :: "n"(NSTAGES - 2) : "memory");
        __syncthreads();

        const uint32_t aSlot = data_base + (uint32_t)slot * STAGE_BYTES;
        const uint32_t bSlot = aSlot + A_BYTES;

#pragma unroll
        for (int ks = 0; ks < 4; ks++) {
            uint32_t a[4][4], b[2][4];
#pragma unroll
            for (int mi = 0; mi < 4; mi++)
                ldsm_x4(a[mi], aSlot + (uint32_t)((aRowBase + mi * 16) * ROWB + ks * 32 + aColSel));
#pragma unroll
            for (int nj = 0; nj < 2; nj++)
                ldsm_x4(b[nj], bSlot + (uint32_t)((bRowBase + nj * 16) * ROWB + ks * 32 + bColSel));
#pragma unroll
            for (int mi = 0; mi < 4; mi++)
#pragma unroll
                for (int nj = 0; nj < 2; nj++) {
                    mma_bf16(c[mi][2 * nj],     a[mi], b[nj][0], b[nj][1]);
                    mma_bf16(c[mi][2 * nj + 1], a[mi], b[nj][2], b[nj][3]);
                }
        }

        const int lt = kt + NSTAGES - 1;
        if (lt < K_TILES) load_stage(data_base, lt % NSTAGES, m0, n0, lt, tid);
        CP_COMMIT();
    }

    // epilogue: f32( bf16( bf16(acc) + bf16(bias) ) ), stored as f32 positional
    const int rbase = m0 + wm * 64 + (lane >> 2);
    const int cbase = n0 + wn * 32 + (lane & 3) * 2;
#pragma unroll
    for (int mi = 0; mi < 4; mi++) {
#pragma unroll
        for (int ni = 0; ni < 4; ni++) {
            int gm = rbase + mi * 16;
            int gn = cbase + ni * 8;
            float b0 = __bfloat162float(__float2bfloat16(bias[gn]));
            float b1 = __bfloat162float(__float2bfloat16(bias[gn + 1]));
            float s00 = __bfloat162float(__float2bfloat16(c[mi][ni][0]));
            float s01 = __bfloat162float(__float2bfloat16(c[mi][ni][1]));
            float s10 = __bfloat162float(__float2bfloat16(c[mi][ni][2]));
            float s11 = __bfloat162float(__float2bfloat16(c[mi][ni][3]));
            float2 v0 = make_float2(__bfloat162float(__float2bfloat16(s00 + b0)),
                                    __bfloat162float(__float2bfloat16(s01 + b1)));
            float2 v1 = make_float2(__bfloat162float(__float2bfloat16(s10 + b0)),
                                    __bfloat162float(__float2bfloat16(s11 + b1)));
            *reinterpret_cast<float2*>(out + (size_t)gm * OUT_F + gn) = v0;
            *reinterpret_cast<float2*>(out + (size_t)(gm + 8) * OUT_F + gn) = v1;
        }
    }
}

// ---------------- launch ----------------
extern "C" void kernel_launch(void* const* d_in, const int* in_sizes, int n_in,
                              void* d_out, int out_size) {
    (void)out_size;
    const float* xf32   = nullptr;   // 4194304  f32 (bf16-valued)
    const float* wf8    = nullptr;   // 58720256 f32 (fp8-valued)
    const float* wscale = nullptr;   // 1        f32
    const float* bias   = nullptr;   // 14336    f32
    for (int i = 0; i < n_in; i++) {
        switch (in_sizes[i]) {
            case 4194304:  xf32   = (const float*)d_in[i]; break;
            case 58720256: wf8    = (const float*)d_in[i]; break;
            case 1:        wscale = (const float*)d_in[i]; break;
            case 14336:    bias   = (const float*)d_in[i]; break;
            default: break;
        }
    }
    float* out = (float*)d_out;

    convert_x_kernel<<<1024, 256>>>(reinterpret_cast<const float4*>(xf32));

    cudaFuncSetAttribute(f8linear_gemm, cudaFuncAttributeMaxDynamicSharedMemorySize,
                         SMEM_DYN_BYTES);
    int grid = (M_ROWS / BM) * (OUT_F / BN);   // 8 * 112 = 896
    f8linear_gemm<<<grid, 256, SMEM_DYN_BYTES>>>(
        reinterpret_cast<const float4*>(wf8), wscale, bias, out);
}